// round 12
// baseline (speedup 1.0000x reference)
#include <cuda_runtime.h>
#include <cuda_fp16.h>
#include <mma.h>

using namespace nvcuda;

#define BTOK 8192
#define IND  1024
#define HID  4096
#define OUTD 1024
#define RHD  128
#define NE   3
#define GCAP 8448            // max padded gathered rows (multiple of 128)
#define MTILES (GCAP / 128)  // 66
#define KPARTS 4

// ---------------- device scratch (EXACT R9 set: fp32/int only — proven clean) ----
__device__ int   g_selected[BTOK];
__device__ int   g_counts[NE];
__device__ int   g_cursor[NE];
__device__ int   g_off[NE + 1];
__device__ int   g_total;
__device__ int   g_gathered[GCAP];
__device__ float g_rh[BTOK * RHD];          // router partial (part 0)
__device__ float g_h[(size_t)GCAP * HID];   // router partials 1-3 (first 12.6MB), then hidden fp32

// ---------------- init ----------------
__global__ void k_init() {
    int i = blockIdx.x * blockDim.x + threadIdx.x;
    if (i < GCAP) g_gathered[i] = -1;
    if (i < NE) { g_counts[i] = 0; g_cursor[i] = 0; }
}

// ---------------- router fp32 GEMM, K-split x4 ----------------
// part 0 partial -> g_rh, parts 1..3 -> g_h slices (consumed by k_logits before GEMM1)
__global__ __launch_bounds__(256)
void k_router(const float* __restrict__ x, const float* __restrict__ w1)
{
    const int BK = 16;
    __shared__ float As[BK][128];
    __shared__ float Bs[BK][128];
    const int m0 = blockIdx.y * 128;
    const int part = blockIdx.z;
    const int kbase = part * (IND / KPARTS);
    const int tid = threadIdx.x;
    const int tx = tid & 15, ty = tid >> 4;

    float c[8][8];
#pragma unroll
    for (int i = 0; i < 8; i++)
#pragma unroll
        for (int j = 0; j < 8; j++) c[i][j] = 0.f;

    for (int k0 = 0; k0 < IND / KPARTS; k0 += BK) {
#pragma unroll
        for (int t = 0; t < 2; t++) {
            int lin = tid + t * 256;
            int row = lin >> 2, kq = (lin & 3) * 4;
            float4 v = *reinterpret_cast<const float4*>(
                x + (size_t)(m0 + row) * IND + kbase + k0 + kq);
            As[kq + 0][row] = v.x; As[kq + 1][row] = v.y;
            As[kq + 2][row] = v.z; As[kq + 3][row] = v.w;
        }
#pragma unroll
        for (int t = 0; t < 2; t++) {
            int lin = tid + t * 256;
            int kk = lin >> 5, nq = (lin & 31) * 4;
            float4 v = *reinterpret_cast<const float4*>(
                w1 + (size_t)(kbase + k0 + kk) * RHD + nq);
            *reinterpret_cast<float4*>(&Bs[kk][nq]) = v;
        }
        __syncthreads();
#pragma unroll
        for (int kk = 0; kk < BK; kk++) {
            float a[8], b[8];
            float4 a0 = *reinterpret_cast<const float4*>(&As[kk][ty * 8]);
            float4 a1 = *reinterpret_cast<const float4*>(&As[kk][ty * 8 + 4]);
            float4 b0 = *reinterpret_cast<const float4*>(&Bs[kk][tx * 8]);
            float4 b1 = *reinterpret_cast<const float4*>(&Bs[kk][tx * 8 + 4]);
            a[0]=a0.x; a[1]=a0.y; a[2]=a0.z; a[3]=a0.w;
            a[4]=a1.x; a[5]=a1.y; a[6]=a1.z; a[7]=a1.w;
            b[0]=b0.x; b[1]=b0.y; b[2]=b0.z; b[3]=b0.w;
            b[4]=b1.x; b[5]=b1.y; b[6]=b1.z; b[7]=b1.w;
#pragma unroll
            for (int i = 0; i < 8; i++)
#pragma unroll
                for (int j = 0; j < 8; j++)
                    c[i][j] = fmaf(a[i], b[j], c[i][j]);
        }
        __syncthreads();
    }
    float* dst = (part == 0) ? g_rh : (g_h + (size_t)(part - 1) * BTOK * RHD);
#pragma unroll
    for (int i = 0; i < 8; i++) {
        float* p = dst + (size_t)(m0 + ty * 8 + i) * RHD + tx * 8;
        *reinterpret_cast<float4*>(p)     = make_float4(c[i][0], c[i][1], c[i][2], c[i][3]);
        *reinterpret_cast<float4*>(p + 4) = make_float4(c[i][4], c[i][5], c[i][6], c[i][7]);
    }
}

// ---------------- logits: sum partials + b1, relu, w2, argmax ----------------
__global__ void k_logits(const float* __restrict__ b1, const float* __restrict__ w2,
                         const float* __restrict__ b2)
{
    __shared__ float w2s[RHD * NE];
    __shared__ float b1s[RHD];
    __shared__ float b2s[NE];
    int tid = threadIdx.x;
    for (int i = tid; i < RHD * NE; i += 128) w2s[i] = w2[i];
    if (tid < RHD) b1s[tid] = b1[tid];
    if (tid < NE) b2s[tid] = b2[tid];
    __syncthreads();

    int token = blockIdx.x * 128 + tid;
    if (token >= BTOK) return;
    const float* p0 = g_rh + (size_t)token * RHD;
    const float* p1 = g_h + (size_t)token * RHD;
    const size_t PS = (size_t)BTOK * RHD;
    float a0 = b2s[0], a1 = b2s[1], a2 = b2s[2];
#pragma unroll 8
    for (int k = 0; k < RHD; k++) {
        float v = p0[k] + p1[k] + p1[PS + k] + p1[2 * PS + k] + b1s[k];
        v = fmaxf(v, 0.f);
        a0 = fmaf(v, w2s[k * NE + 0], a0);
        a1 = fmaf(v, w2s[k * NE + 1], a1);
        a2 = fmaf(v, w2s[k * NE + 2], a2);
    }
    int sel = 0; float best = a0;
    if (a1 > best) { best = a1; sel = 1; }
    if (a2 > best) { best = a2; sel = 2; }
    g_selected[token] = sel;
    atomicAdd(&g_counts[sel], 1);
}

__global__ void k_offsets()
{
    int off = 0;
    g_off[0] = 0;
    for (int e = 0; e < NE; e++) {
        int mpad = ((g_counts[e] + 127) / 128) * 128;
        off += mpad;
        g_off[e + 1] = off;
    }
    g_total = off;
}

__global__ void k_scatter()
{
    int b = blockIdx.x * 256 + threadIdx.x;
    if (b >= BTOK) return;
    int e = g_selected[b];
    int pos = atomicAdd(&g_cursor[e], 1);
    g_gathered[g_off[e] + pos] = b;
}

// ---------------- WMMA fp16 expert GEMM, double-buffered (R9 structure) ----------
// fp32 global tiles converted to fp16 at smem store; wmma fp32 accumulate.
// As[buf][k][m] col-major (LDS=136), Bs[buf][k][n] row-major (LDS=136).
// 8 warps, warp tile 32x64. One __syncthreads per 16-k chunk.
template<int K, int LDA, int N, int LDC,
         bool GATHER, bool A_IS_H, int C_SEL, bool RELU_EPI, bool SCATTER>
__global__ __launch_bounds__(256)
void wgemm128(const float* __restrict__ Asrc, const float* __restrict__ Bsrc,
              const float* __restrict__ bias, float* __restrict__ Cdst)
{
    const int BK = 16, LDS = 136;
    __shared__ __align__(32) __half As[2][BK][LDS];
    __shared__ __align__(32) __half Bs[2][BK][LDS];
    __shared__ __align__(32) float stage[8][16][20];

    const int m0 = blockIdx.y * 128;
    if (m0 >= g_total) return;
    int e = 0;
    if (m0 >= g_off[1]) e = (m0 >= g_off[2]) ? 2 : 1;
    const float* Bp = Bsrc + (size_t)e * K * N;
    const float* bp = bias + (size_t)e * N;

    const int n0 = blockIdx.x * 128;
    const int tid = threadIdx.x;
    const int wid = tid >> 5, lane = tid & 31;
    const int wm = wid & 3, wn = wid >> 2;   // 4x2 warp grid, 32x64 warp tile

    const float* Ab = A_IS_H ? (const float*)g_h : Asrc;

    // per-thread load slots (R9 mapping)
    const float* arow[2];
    int akq[2];
#pragma unroll
    for (int t = 0; t < 2; t++) {
        int lin = tid + t * 256;
        int row = lin >> 2;
        akq[t] = (lin & 3) * 4;
        int r = GATHER ? g_gathered[m0 + row] : (m0 + row);
        arow[t] = (r >= 0) ? (Ab + (size_t)r * LDA) : (const float*)0;
    }
    int arowi[2] = { tid >> 2, (tid >> 2) + 64 };
    int bkk[2]   = { tid >> 5, (tid >> 5) + 8 };
    int bnq      = (tid & 31) * 4;

    wmma::fragment<wmma::accumulator, 16, 16, 16, float> cf[2][4];
#pragma unroll
    for (int i = 0; i < 2; i++)
#pragma unroll
        for (int j = 0; j < 4; j++) wmma::fill_fragment(cf[i][j], 0.f);

    float4 pa[2], pb[2];
    // prefetch chunk 0
#pragma unroll
    for (int t = 0; t < 2; t++) {
        pa[t] = arow[t] ? *reinterpret_cast<const float4*>(arow[t] + akq[t])
                        : make_float4(0.f, 0.f, 0.f, 0.f);
        pb[t] = *reinterpret_cast<const float4*>(Bp + (size_t)bkk[t] * N + n0 + bnq);
    }
    // store chunk 0 into buffer 0
#pragma unroll
    for (int t = 0; t < 2; t++) {
        As[0][akq[t] + 0][arowi[t]] = __float2half_rn(pa[t].x);
        As[0][akq[t] + 1][arowi[t]] = __float2half_rn(pa[t].y);
        As[0][akq[t] + 2][arowi[t]] = __float2half_rn(pa[t].z);
        As[0][akq[t] + 3][arowi[t]] = __float2half_rn(pa[t].w);
        __half2 h01 = __floats2half2_rn(pb[t].x, pb[t].y);
        __half2 h23 = __floats2half2_rn(pb[t].z, pb[t].w);
        *reinterpret_cast<__half2*>(&Bs[0][bkk[t]][bnq])     = h01;
        *reinterpret_cast<__half2*>(&Bs[0][bkk[t]][bnq + 2]) = h23;
    }

    const int NCH = K / BK;
    for (int ch = 0; ch < NCH; ch++) {
        __syncthreads();   // buf (ch&1) fully stored; prior compute on other buf done
        const int buf = ch & 1;

        // prefetch chunk ch+1 to registers
        if (ch + 1 < NCH) {
            int kn = (ch + 1) * BK;
#pragma unroll
            for (int t = 0; t < 2; t++) {
                pa[t] = arow[t] ? *reinterpret_cast<const float4*>(arow[t] + kn + akq[t])
                                : make_float4(0.f, 0.f, 0.f, 0.f);
                pb[t] = *reinterpret_cast<const float4*>(
                    Bp + (size_t)(kn + bkk[t]) * N + n0 + bnq);
            }
        }

        // compute current buffer
        wmma::fragment<wmma::matrix_a, 16, 16, 16, __half, wmma::col_major> af[2];
        wmma::fragment<wmma::matrix_b, 16, 16, 16, __half, wmma::row_major> bf[4];
#pragma unroll
        for (int mf = 0; mf < 2; mf++)
            wmma::load_matrix_sync(af[mf], &As[buf][0][wm * 32 + mf * 16], LDS);
#pragma unroll
        for (int nf = 0; nf < 4; nf++)
            wmma::load_matrix_sync(bf[nf], &Bs[buf][0][wn * 64 + nf * 16], LDS);
#pragma unroll
        for (int mf = 0; mf < 2; mf++)
#pragma unroll
            for (int nf = 0; nf < 4; nf++)
                wmma::mma_sync(cf[mf][nf], af[mf], bf[nf], cf[mf][nf]);

        // store chunk ch+1 into the other buffer (safe: prior compute on it finished)
        if (ch + 1 < NCH) {
            const int nb = (ch + 1) & 1;
#pragma unroll
            for (int t = 0; t < 2; t++) {
                As[nb][akq[t] + 0][arowi[t]] = __float2half_rn(pa[t].x);
                As[nb][akq[t] + 1][arowi[t]] = __float2half_rn(pa[t].y);
                As[nb][akq[t] + 2][arowi[t]] = __float2half_rn(pa[t].z);
                As[nb][akq[t] + 3][arowi[t]] = __float2half_rn(pa[t].w);
                __half2 h01 = __floats2half2_rn(pb[t].x, pb[t].y);
                __half2 h23 = __floats2half2_rn(pb[t].z, pb[t].w);
                *reinterpret_cast<__half2*>(&Bs[nb][bkk[t]][bnq])     = h01;
                *reinterpret_cast<__half2*>(&Bs[nb][bkk[t]][bnq + 2]) = h23;
            }
        }
    }

    // ---------------- epilogue: per-warp 16x16 staging (ld=20) ----------------
    float* Cbase = (C_SEL == 0) ? Cdst : (float*)g_h;
#pragma unroll
    for (int mf = 0; mf < 2; mf++)
#pragma unroll
        for (int nf = 0; nf < 4; nf++) {
            wmma::store_matrix_sync(&stage[wid][0][0], cf[mf][nf], 20, wmma::mem_row_major);
            __syncwarp();
            int rb = m0 + wm * 32 + mf * 16;
            int cb = n0 + wn * 64 + nf * 16;
#pragma unroll
            for (int i = 0; i < 8; i++) {
                int idx = lane + i * 32;
                int rr = idx >> 4, cc = idx & 15;
                int row = rb + rr;
                int col = cb + cc;
                float v = stage[wid][rr][cc] + bp[col];
                if (RELU_EPI) v = fmaxf(v, 0.f);
                int r = row;
                if (SCATTER) {
                    r = g_gathered[row];
                    if (r < 0) continue;
                }
                Cbase[(size_t)r * LDC + col] = v;
            }
            __syncwarp();
        }
}

__global__ void k_stats(float* out, int out_size)
{
    int i = threadIdx.x;
    if (i < NE && out_size >= BTOK * OUTD + NE)
        out[(size_t)BTOK * OUTD + i] = (float)g_counts[i];
}

// ---------------- launch ----------------
extern "C" void kernel_launch(void* const* d_in, const int* in_sizes, int n_in,
                              void* d_out, int out_size)
{
    const float* x   = (const float*)d_in[0];
    const float* rw1 = (const float*)d_in[1];
    const float* rb1 = (const float*)d_in[2];
    const float* rw2 = (const float*)d_in[3];
    const float* rb2 = (const float*)d_in[4];
    const float* ew1 = (const float*)d_in[5];
    const float* eb1 = (const float*)d_in[6];
    const float* ew2 = (const float*)d_in[7];
    const float* eb2 = (const float*)d_in[8];
    float* out = (float*)d_out;

    (void)in_sizes; (void)n_in;

    k_init<<<(GCAP + 255) / 256, 256>>>();

    // Router: K-split x4 fp32 partials, then fused bias/relu/logits/argmax
    k_router<<<dim3(1, BTOK / 128, KPARTS), 256>>>(x, rw1);
    k_logits<<<BTOK / 128, 128>>>(rb1, rw2, rb2);
    k_offsets<<<1, 1>>>();
    k_scatter<<<BTOK / 256, 256>>>();

    // Expert GEMM1: h = relu(Xg @ W1[e] + b1[e])   [total x 4096]  (wmma fp16)
    wgemm128<1024, 1024, 4096, 4096, true, false, 2, true, false>
        <<<dim3(HID / 128, MTILES), 256>>>(x, ew1, eb1, nullptr);

    // Expert GEMM2: y = h @ W2[e] + b2[e], scatter to out[token]  (wmma fp16)
    wgemm128<4096, 4096, 1024, 1024, false, true, 0, false, true>
        <<<dim3(OUTD / 128, MTILES), 256>>>(nullptr, ew2, eb2, out);

    k_stats<<<1, 32>>>(out, out_size);
}

// round 14
// speedup vs baseline: 1.1446x; 1.1446x over previous
#include <cuda_runtime.h>
#include <cuda_fp16.h>
#include <mma.h>
#include <cstdint>

using namespace nvcuda;

#define BTOK 8192
#define IND  1024
#define HID  4096
#define OUTD 1024
#define RHD  128
#define NE   3
#define GCAP 8448
#define MTILES (GCAP / 128)  // 66
#define KPARTS 4

// single fused scratch (float-typed), offsets in floats:
#define OFF_H   ((size_t)0)                          // packed fp16 hidden: GCAP*HID/2 floats
                                                     // (head doubles as 4 router partial blocks)
#define OFF_W1P ((size_t)GCAP * HID / 2)             // packed w1: NE*IND*HID/2
#define OFF_W2P (OFF_W1P + (size_t)NE * IND * HID / 2)
#define BUFSZ   (OFF_W2P + (size_t)NE * HID * OUTD / 2)   // 29,884,416 floats = 119.5 MB
#define W1Q     (NE * IND * HID / 4)                 // 3,145,728 quads
#define W2Q     (NE * HID * OUTD / 4)

// ---------------- device scratch: 7 globals total (clean signature) ----------------
__device__ int   g_selected[BTOK];
__device__ int   g_counts[NE];
__device__ int   g_cursor[NE];
__device__ int   g_off[NE + 1];
__device__ int   g_total;
__device__ int   g_gathered[GCAP];
__device__ float g_buf[BUFSZ];

__device__ __forceinline__ float pack2(float a, float b) {
    __half2 h = __floats2half2_rn(a, b);
    uint32_t u = *reinterpret_cast<uint32_t*>(&h);
    return __uint_as_float(u);
}

// ---------------- init + weight packing (fused; no extra kernels) ----------------
__global__ void k_init(const float* __restrict__ ew1, const float* __restrict__ ew2)
{
    int i = blockIdx.x * blockDim.x + threadIdx.x;
    if (i < GCAP) g_gathered[i] = -1;
    if (i < NE) { g_counts[i] = 0; g_cursor[i] = 0; }
    if (i < W1Q) {
        float4 v = *reinterpret_cast<const float4*>(ew1 + (size_t)i * 4);
        *reinterpret_cast<float2*>(g_buf + OFF_W1P + (size_t)i * 2) =
            make_float2(pack2(v.x, v.y), pack2(v.z, v.w));
    }
    if (i < W2Q) {
        float4 v = *reinterpret_cast<const float4*>(ew2 + (size_t)i * 4);
        *reinterpret_cast<float2*>(g_buf + OFF_W2P + (size_t)i * 2) =
            make_float2(pack2(v.x, v.y), pack2(v.z, v.w));
    }
}

// ---------------- router fp32 GEMM, K-split x4, partials -> g_buf head ----------
__global__ __launch_bounds__(256)
void k_router(const float* __restrict__ x, const float* __restrict__ w1)
{
    const int BK = 16;
    __shared__ float As[BK][128];
    __shared__ float Bs[BK][128];
    const int m0 = blockIdx.y * 128;
    const int part = blockIdx.z;
    const int kbase = part * (IND / KPARTS);
    const int tid = threadIdx.x;
    const int tx = tid & 15, ty = tid >> 4;

    float c[8][8];
#pragma unroll
    for (int i = 0; i < 8; i++)
#pragma unroll
        for (int j = 0; j < 8; j++) c[i][j] = 0.f;

    for (int k0 = 0; k0 < IND / KPARTS; k0 += BK) {
#pragma unroll
        for (int t = 0; t < 2; t++) {
            int lin = tid + t * 256;
            int row = lin >> 2, kq = (lin & 3) * 4;
            float4 v = *reinterpret_cast<const float4*>(
                x + (size_t)(m0 + row) * IND + kbase + k0 + kq);
            As[kq + 0][row] = v.x; As[kq + 1][row] = v.y;
            As[kq + 2][row] = v.z; As[kq + 3][row] = v.w;
        }
#pragma unroll
        for (int t = 0; t < 2; t++) {
            int lin = tid + t * 256;
            int kk = lin >> 5, nq = (lin & 31) * 4;
            float4 v = *reinterpret_cast<const float4*>(
                w1 + (size_t)(kbase + k0 + kk) * RHD + nq);
            *reinterpret_cast<float4*>(&Bs[kk][nq]) = v;
        }
        __syncthreads();
#pragma unroll
        for (int kk = 0; kk < BK; kk++) {
            float a[8], b[8];
            float4 a0 = *reinterpret_cast<const float4*>(&As[kk][ty * 8]);
            float4 a1 = *reinterpret_cast<const float4*>(&As[kk][ty * 8 + 4]);
            float4 b0 = *reinterpret_cast<const float4*>(&Bs[kk][tx * 8]);
            float4 b1 = *reinterpret_cast<const float4*>(&Bs[kk][tx * 8 + 4]);
            a[0]=a0.x; a[1]=a0.y; a[2]=a0.z; a[3]=a0.w;
            a[4]=a1.x; a[5]=a1.y; a[6]=a1.z; a[7]=a1.w;
            b[0]=b0.x; b[1]=b0.y; b[2]=b0.z; b[3]=b0.w;
            b[4]=b1.x; b[5]=b1.y; b[6]=b1.z; b[7]=b1.w;
#pragma unroll
            for (int i = 0; i < 8; i++)
#pragma unroll
                for (int j = 0; j < 8; j++)
                    c[i][j] = fmaf(a[i], b[j], c[i][j]);
        }
        __syncthreads();
    }
    float* dst = g_buf + (size_t)part * BTOK * RHD;
#pragma unroll
    for (int i = 0; i < 8; i++) {
        float* p = dst + (size_t)(m0 + ty * 8 + i) * RHD + tx * 8;
        *reinterpret_cast<float4*>(p)     = make_float4(c[i][0], c[i][1], c[i][2], c[i][3]);
        *reinterpret_cast<float4*>(p + 4) = make_float4(c[i][4], c[i][5], c[i][6], c[i][7]);
    }
}

// ---------------- logits: sum partials + b1, relu, w2, argmax ----------------
__global__ void k_logits(const float* __restrict__ b1, const float* __restrict__ w2,
                         const float* __restrict__ b2)
{
    __shared__ float w2s[RHD * NE];
    __shared__ float b1s[RHD];
    __shared__ float b2s[NE];
    int tid = threadIdx.x;
    for (int i = tid; i < RHD * NE; i += 128) w2s[i] = w2[i];
    if (tid < RHD) b1s[tid] = b1[tid];
    if (tid < NE) b2s[tid] = b2[tid];
    __syncthreads();

    int token = blockIdx.x * 128 + tid;
    if (token >= BTOK) return;
    const float* p0 = g_buf + (size_t)token * RHD;
    const size_t PS = (size_t)BTOK * RHD;
    float a0 = b2s[0], a1 = b2s[1], a2 = b2s[2];
#pragma unroll 8
    for (int k = 0; k < RHD; k++) {
        float v = p0[k] + p0[PS + k] + p0[2 * PS + k] + p0[3 * PS + k] + b1s[k];
        v = fmaxf(v, 0.f);
        a0 = fmaf(v, w2s[k * NE + 0], a0);
        a1 = fmaf(v, w2s[k * NE + 1], a1);
        a2 = fmaf(v, w2s[k * NE + 2], a2);
    }
    int sel = 0; float best = a0;
    if (a1 > best) { best = a1; sel = 1; }
    if (a2 > best) { best = a2; sel = 2; }
    g_selected[token] = sel;
    atomicAdd(&g_counts[sel], 1);
}

__global__ void k_offsets()
{
    int off = 0;
    g_off[0] = 0;
    for (int e = 0; e < NE; e++) {
        int mpad = ((g_counts[e] + 127) / 128) * 128;
        off += mpad;
        g_off[e + 1] = off;
    }
    g_total = off;
}

__global__ void k_scatter()
{
    int b = blockIdx.x * 256 + threadIdx.x;
    if (b >= BTOK) return;
    int e = g_selected[b];
    int pos = atomicAdd(&g_cursor[e], 1);
    g_gathered[g_off[e] + pos] = b;
}

// ---------------- WMMA GEMM, 128x128 tile, BK=16, double-buffered ----------------
// EPI==1: A = x fp32 (gather, convert at smem store), B = packed w1;
//         epilogue: g_buf[OFF_H] = packed fp16(relu(D + b1)).
// EPI==2: A = packed h, B = packed w2; epilogue: out[g_gathered[row]] = D + b2.
template<int K, int NB, int EPI>
__global__ __launch_bounds__(256)
void wgemm(const float* __restrict__ Axf, const float* __restrict__ biasb,
           float* __restrict__ Cout)
{
    const int BK = 16;
    __shared__ __align__(16) __half As[2][128][24];   // row-major, ldm 24 (48B)
    __shared__ __align__(16) __half Bs[2][BK][136];   // row-major, ldm 136 (272B)
    __shared__ __align__(16) float stage[8][16][20];

    const int m0 = blockIdx.y * 128;
    if (m0 >= g_total) return;
    int e = (m0 >= g_off[1]) ? ((m0 >= g_off[2]) ? 2 : 1) : 0;
    const int n0 = blockIdx.x * 128;
    const float* Bp = (EPI == 1 ? g_buf + OFF_W1P : g_buf + OFF_W2P) + (size_t)e * K * NB / 2;
    const float* bp = biasb + (size_t)e * NB;

    const int tid = threadIdx.x;
    const int wid = tid >> 5, lane = tid & 31;
    const int wm = wid & 3, wn = wid >> 2;   // 4x2 warp grid, 32x64 warp tile

    // ---- A load slots ----
    // EPI1 (fp32 gather): slot lin = tid + 256*t: row = lin>>2, kq = (lin&3)*4
    const float* arow[2];
    int akq[2], arr[2];
    // EPI2 (packed): row = tid>>1, cq = tid&1 (8 halves each)
    const float* gA2 = nullptr;
    int a2row = 0, a2cq = 0;
    if (EPI == 1) {
#pragma unroll
        for (int t = 0; t < 2; t++) {
            int lin = tid + t * 256;
            arr[t] = lin >> 2;
            akq[t] = (lin & 3) * 4;
            int r = g_gathered[m0 + arr[t]];
            arow[t] = (r >= 0) ? (Axf + (size_t)r * K) : (const float*)0;
        }
    } else {
        a2row = tid >> 1; a2cq = tid & 1;
        gA2 = g_buf + OFF_H + (size_t)(m0 + a2row) * (K / 2) + a2cq * 4;
    }
    // ---- B load slot: krow = tid>>4, cq = tid&15 (8 halves each) ----
    const int bkr = tid >> 4, bcq = tid & 15;
    const float* gB = Bp + (size_t)bkr * (NB / 2) + n0 / 2 + bcq * 4;

    wmma::fragment<wmma::accumulator, 16, 16, 16, float> cf[2][4];
#pragma unroll
    for (int i = 0; i < 2; i++)
#pragma unroll
        for (int j = 0; j < 4; j++) wmma::fill_fragment(cf[i][j], 0.f);

    float4 pa[2];        // EPI1 prefetch
    uint4  pa2;          // EPI2 prefetch
    uint4  pb;

    // prefetch + store chunk 0 into buffer 0
    if (EPI == 1) {
#pragma unroll
        for (int t = 0; t < 2; t++)
            pa[t] = arow[t] ? *reinterpret_cast<const float4*>(arow[t] + akq[t])
                            : make_float4(0.f, 0.f, 0.f, 0.f);
    } else {
        pa2 = *reinterpret_cast<const uint4*>(gA2);
    }
    pb = *reinterpret_cast<const uint4*>(gB);

    if (EPI == 1) {
#pragma unroll
        for (int t = 0; t < 2; t++) {
            __half2 h01 = __floats2half2_rn(pa[t].x, pa[t].y);
            __half2 h23 = __floats2half2_rn(pa[t].z, pa[t].w);
            *reinterpret_cast<__half2*>(&As[0][arr[t]][akq[t]])     = h01;
            *reinterpret_cast<__half2*>(&As[0][arr[t]][akq[t] + 2]) = h23;
        }
    } else {
        *reinterpret_cast<uint4*>(&As[0][a2row][a2cq * 8]) = pa2;
    }
    *reinterpret_cast<uint4*>(&Bs[0][bkr][bcq * 8]) = pb;

    const int NCH = K / BK;
    for (int ch = 0; ch < NCH; ch++) {
        __syncthreads();
        const int buf = ch & 1;

        // prefetch chunk ch+1
        if (ch + 1 < NCH) {
            int kn = (ch + 1) * BK;
            if (EPI == 1) {
#pragma unroll
                for (int t = 0; t < 2; t++)
                    pa[t] = arow[t] ? *reinterpret_cast<const float4*>(arow[t] + kn + akq[t])
                                    : make_float4(0.f, 0.f, 0.f, 0.f);
            } else {
                pa2 = *reinterpret_cast<const uint4*>(gA2 + kn / 2);
            }
            pb = *reinterpret_cast<const uint4*>(gB + (size_t)kn * (NB / 2));
        }

        // compute current buffer
        wmma::fragment<wmma::matrix_a, 16, 16, 16, __half, wmma::row_major> af[2];
        wmma::fragment<wmma::matrix_b, 16, 16, 16, __half, wmma::row_major> bf[4];
#pragma unroll
        for (int mf = 0; mf < 2; mf++)
            wmma::load_matrix_sync(af[mf], &As[buf][wm * 32 + mf * 16][0], 24);
#pragma unroll
        for (int nf = 0; nf < 4; nf++)
            wmma::load_matrix_sync(bf[nf], &Bs[buf][0][wn * 64 + nf * 16], 136);
#pragma unroll
        for (int mf = 0; mf < 2; mf++)
#pragma unroll
            for (int nf = 0; nf < 4; nf++)
                wmma::mma_sync(cf[mf][nf], af[mf], bf[nf], cf[mf][nf]);

        // store chunk ch+1 into other buffer
        if (ch + 1 < NCH) {
            const int nb = (ch + 1) & 1;
            if (EPI == 1) {
#pragma unroll
                for (int t = 0; t < 2; t++) {
                    __half2 h01 = __floats2half2_rn(pa[t].x, pa[t].y);
                    __half2 h23 = __floats2half2_rn(pa[t].z, pa[t].w);
                    *reinterpret_cast<__half2*>(&As[nb][arr[t]][akq[t]])     = h01;
                    *reinterpret_cast<__half2*>(&As[nb][arr[t]][akq[t] + 2]) = h23;
                }
            } else {
                *reinterpret_cast<uint4*>(&As[nb][a2row][a2cq * 8]) = pa2;
            }
            *reinterpret_cast<uint4*>(&Bs[nb][bkr][bcq * 8]) = pb;
        }
    }

    // ---------------- epilogue: per-warp 16x16 staging (ld=20) ----------------
#pragma unroll
    for (int mf = 0; mf < 2; mf++)
#pragma unroll
        for (int nf = 0; nf < 4; nf++) {
            wmma::store_matrix_sync(&stage[wid][0][0], cf[mf][nf], 20, wmma::mem_row_major);
            __syncwarp();
            int rb = m0 + wm * 32 + mf * 16;
            int cb = n0 + wn * 64 + nf * 16;
#pragma unroll
            for (int i = 0; i < 4; i++) {
                int p = lane + i * 32;            // 128 pairs cover 16x16
                int rr = p >> 3, cc = (p & 7) * 2;
                int row = rb + rr;
                int col = cb + cc;
                float v0 = stage[wid][rr][cc]     + bp[col];
                float v1 = stage[wid][rr][cc + 1] + bp[col + 1];
                if (EPI == 1) {
                    v0 = fmaxf(v0, 0.f);
                    v1 = fmaxf(v1, 0.f);
                    g_buf[OFF_H + (size_t)row * (HID / 2) + col / 2] = pack2(v0, v1);
                } else {
                    int r = g_gathered[row];
                    if (r >= 0)
                        *reinterpret_cast<float2*>(Cout + (size_t)r * NB + col) =
                            make_float2(v0, v1);
                }
            }
            __syncwarp();
        }
}

__global__ void k_stats(float* out, int out_size)
{
    int i = threadIdx.x;
    if (i < NE && out_size >= BTOK * OUTD + NE)
        out[(size_t)BTOK * OUTD + i] = (float)g_counts[i];
}

// ---------------- launch (8 launches, 8 kernel functions) ----------------
extern "C" void kernel_launch(void* const* d_in, const int* in_sizes, int n_in,
                              void* d_out, int out_size)
{
    const float* x   = (const float*)d_in[0];
    const float* rw1 = (const float*)d_in[1];
    const float* rb1 = (const float*)d_in[2];
    const float* rw2 = (const float*)d_in[3];
    const float* rb2 = (const float*)d_in[4];
    const float* ew1 = (const float*)d_in[5];
    const float* eb1 = (const float*)d_in[6];
    const float* ew2 = (const float*)d_in[7];
    const float* eb2 = (const float*)d_in[8];
    float* out = (float*)d_out;

    (void)in_sizes; (void)n_in;

    // init state + pack both weight tensors to fp16 (inside g_buf)
    k_init<<<(W1Q + 255) / 256, 256>>>(ew1, ew2);

    // Router: K-split x4 fp32 partials (g_buf head), then fused logits/argmax
    k_router<<<dim3(1, BTOK / 128, KPARTS), 256>>>(x, rw1);
    k_logits<<<BTOK / 128, 128>>>(rb1, rw2, rb2);
    k_offsets<<<1, 1>>>();
    k_scatter<<<BTOK / 256, 256>>>();

    // GEMM1: h(packed) = fp16(relu(Xg @ W1[e] + b1[e]))
    wgemm<IND, HID, 1><<<dim3(HID / 128, MTILES), 256>>>(x, eb1, nullptr);

    // GEMM2: out[token] = h @ W2[e] + b2[e]
    wgemm<HID, OUTD, 2><<<dim3(OUTD / 128, MTILES), 256>>>(nullptr, eb2, out);

    k_stats<<<1, 32>>>(out, out_size);
}

// round 16
// speedup vs baseline: 1.3626x; 1.1905x over previous
#include <cuda_runtime.h>
#include <cuda_fp16.h>
#include <mma.h>
#include <cstdint>

using namespace nvcuda;

#define BTOK 8192
#define IND  1024
#define HID  4096
#define OUTD 1024
#define RHD  128
#define NE   3
#define GCAP 8448
#define MTILES (GCAP / 128)  // 66
#define KPARTS 4

// single fused scratch (float-typed), offsets in floats:
#define OFF_H   ((size_t)0)
#define OFF_W1P ((size_t)GCAP * HID / 2)
#define OFF_W2P (OFF_W1P + (size_t)NE * IND * HID / 2)
#define BUFSZ   (OFF_W2P + (size_t)NE * HID * OUTD / 2)
#define W1Q     (NE * IND * HID / 4)
#define W2Q     (NE * HID * OUTD / 4)

// ---------------- device scratch: 7 globals (clean signature) ----------------
__device__ int   g_selected[BTOK];
__device__ int   g_counts[NE];
__device__ int   g_cursor[NE];
__device__ int   g_off[NE + 1];
__device__ int   g_total;
__device__ int   g_gathered[GCAP];
__device__ float g_buf[BUFSZ];

__device__ __forceinline__ float pack2(float a, float b) {
    __half2 h = __floats2half2_rn(a, b);
    uint32_t u = *reinterpret_cast<uint32_t*>(&h);
    return __uint_as_float(u);
}

// ---------------- init + weight packing ----------------
__global__ void k_init(const float* __restrict__ ew1, const float* __restrict__ ew2)
{
    int i = blockIdx.x * blockDim.x + threadIdx.x;
    if (i < GCAP) g_gathered[i] = -1;
    if (i < NE) { g_counts[i] = 0; g_cursor[i] = 0; }
    if (i < W1Q) {
        float4 v = *reinterpret_cast<const float4*>(ew1 + (size_t)i * 4);
        *reinterpret_cast<float2*>(g_buf + OFF_W1P + (size_t)i * 2) =
            make_float2(pack2(v.x, v.y), pack2(v.z, v.w));
    }
    if (i < W2Q) {
        float4 v = *reinterpret_cast<const float4*>(ew2 + (size_t)i * 4);
        *reinterpret_cast<float2*>(g_buf + OFF_W2P + (size_t)i * 2) =
            make_float2(pack2(v.x, v.y), pack2(v.z, v.w));
    }
}

// ---------------- router fp32 GEMM, K-split x4 ----------------
__global__ __launch_bounds__(256)
void k_router(const float* __restrict__ x, const float* __restrict__ w1)
{
    const int BK = 16;
    __shared__ float As[BK][128];
    __shared__ float Bs[BK][128];
    const int m0 = blockIdx.y * 128;
    const int part = blockIdx.z;
    const int kbase = part * (IND / KPARTS);
    const int tid = threadIdx.x;
    const int tx = tid & 15, ty = tid >> 4;

    float c[8][8];
#pragma unroll
    for (int i = 0; i < 8; i++)
#pragma unroll
        for (int j = 0; j < 8; j++) c[i][j] = 0.f;

    for (int k0 = 0; k0 < IND / KPARTS; k0 += BK) {
#pragma unroll
        for (int t = 0; t < 2; t++) {
            int lin = tid + t * 256;
            int row = lin >> 2, kq = (lin & 3) * 4;
            float4 v = *reinterpret_cast<const float4*>(
                x + (size_t)(m0 + row) * IND + kbase + k0 + kq);
            As[kq + 0][row] = v.x; As[kq + 1][row] = v.y;
            As[kq + 2][row] = v.z; As[kq + 3][row] = v.w;
        }
#pragma unroll
        for (int t = 0; t < 2; t++) {
            int lin = tid + t * 256;
            int kk = lin >> 5, nq = (lin & 31) * 4;
            float4 v = *reinterpret_cast<const float4*>(
                w1 + (size_t)(kbase + k0 + kk) * RHD + nq);
            *reinterpret_cast<float4*>(&Bs[kk][nq]) = v;
        }
        __syncthreads();
#pragma unroll
        for (int kk = 0; kk < BK; kk++) {
            float a[8], b[8];
            float4 a0 = *reinterpret_cast<const float4*>(&As[kk][ty * 8]);
            float4 a1 = *reinterpret_cast<const float4*>(&As[kk][ty * 8 + 4]);
            float4 b0 = *reinterpret_cast<const float4*>(&Bs[kk][tx * 8]);
            float4 b1 = *reinterpret_cast<const float4*>(&Bs[kk][tx * 8 + 4]);
            a[0]=a0.x; a[1]=a0.y; a[2]=a0.z; a[3]=a0.w;
            a[4]=a1.x; a[5]=a1.y; a[6]=a1.z; a[7]=a1.w;
            b[0]=b0.x; b[1]=b0.y; b[2]=b0.z; b[3]=b0.w;
            b[4]=b1.x; b[5]=b1.y; b[6]=b1.z; b[7]=b1.w;
#pragma unroll
            for (int i = 0; i < 8; i++)
#pragma unroll
                for (int j = 0; j < 8; j++)
                    c[i][j] = fmaf(a[i], b[j], c[i][j]);
        }
        __syncthreads();
    }
    float* dst = g_buf + (size_t)part * BTOK * RHD;
#pragma unroll
    for (int i = 0; i < 8; i++) {
        float* p = dst + (size_t)(m0 + ty * 8 + i) * RHD + tx * 8;
        *reinterpret_cast<float4*>(p)     = make_float4(c[i][0], c[i][1], c[i][2], c[i][3]);
        *reinterpret_cast<float4*>(p + 4) = make_float4(c[i][4], c[i][5], c[i][6], c[i][7]);
    }
}

// ---------------- logits ----------------
__global__ void k_logits(const float* __restrict__ b1, const float* __restrict__ w2,
                         const float* __restrict__ b2)
{
    __shared__ float w2s[RHD * NE];
    __shared__ float b1s[RHD];
    __shared__ float b2s[NE];
    int tid = threadIdx.x;
    for (int i = tid; i < RHD * NE; i += 128) w2s[i] = w2[i];
    if (tid < RHD) b1s[tid] = b1[tid];
    if (tid < NE) b2s[tid] = b2[tid];
    __syncthreads();

    int token = blockIdx.x * 128 + tid;
    if (token >= BTOK) return;
    const float* p0 = g_buf + (size_t)token * RHD;
    const size_t PS = (size_t)BTOK * RHD;
    float a0 = b2s[0], a1 = b2s[1], a2 = b2s[2];
#pragma unroll 8
    for (int k = 0; k < RHD; k++) {
        float v = p0[k] + p0[PS + k] + p0[2 * PS + k] + p0[3 * PS + k] + b1s[k];
        v = fmaxf(v, 0.f);
        a0 = fmaf(v, w2s[k * NE + 0], a0);
        a1 = fmaf(v, w2s[k * NE + 1], a1);
        a2 = fmaf(v, w2s[k * NE + 2], a2);
    }
    int sel = 0; float best = a0;
    if (a1 > best) { best = a1; sel = 1; }
    if (a2 > best) { best = a2; sel = 2; }
    g_selected[token] = sel;
    atomicAdd(&g_counts[sel], 1);
}

__global__ void k_offsets()
{
    int off = 0;
    g_off[0] = 0;
    for (int e = 0; e < NE; e++) {
        int mpad = ((g_counts[e] + 127) / 128) * 128;
        off += mpad;
        g_off[e + 1] = off;
    }
    g_total = off;
}

__global__ void k_scatter()
{
    int b = blockIdx.x * 256 + threadIdx.x;
    if (b >= BTOK) return;
    int e = g_selected[b];
    int pos = atomicAdd(&g_cursor[e], 1);
    g_gathered[g_off[e] + pos] = b;
}

// ---------------- WMMA GEMM, 128x128 tile, BK=32, double-buffered ----------------
// EPI==1: A = x fp32 (gather+convert at smem store), B = packed w1;
//         epilogue -> packed fp16(relu(D+b1)) into g_buf[OFF_H].
// EPI==2: A = packed h, B = packed w2; epilogue -> out[g_gathered[row]] = D + b2.
template<int K, int NB, int EPI>
__global__ __launch_bounds__(256)
void wgemm(const float* __restrict__ Axf, const float* __restrict__ biasb,
           float* __restrict__ Cout)
{
    const int BK = 32;
    __shared__ __align__(16) __half As[2][128][40];   // row-major, ldm 40
    __shared__ __align__(16) __half Bs[2][BK][136];   // row-major, ldm 136
    __shared__ __align__(16) float stage[8][16][20];  // total smem 48128 B

    const int m0 = blockIdx.y * 128;
    if (m0 >= g_total) return;
    int e = (m0 >= g_off[1]) ? ((m0 >= g_off[2]) ? 2 : 1) : 0;
    const int n0 = blockIdx.x * 128;
    const float* Bp = (EPI == 1 ? g_buf + OFF_W1P : g_buf + OFF_W2P) + (size_t)e * K * NB / 2;
    const float* bp = biasb + (size_t)e * NB;

    const int tid = threadIdx.x;
    const int wid = tid >> 5, lane = tid & 31;
    const int wm = wid & 3, wn = wid >> 2;   // 4x2 warp grid, 32x64 warp tile

    // ---- A load slots ----
    // EPI1 fp32: 128 rows x 8 float4/row = 1024 slots; u = tid+256*t (t<4):
    //   row = u>>3 (0..127), quad = u&7; half-cols quad*4..+3
    // EPI2 packed: 128 rows x 4 uint4/row (32 halves = 4 x 8) = 512 slots;
    //   u = tid+256*t (t<2): row = u>>2 (0..127), chunk = u&3; half-cols chunk*8..+7
    const float* arow[4];
    int arr4[4], aq4[4];
    const float* gA2[2];
    int a2r[2], a2c[2];
    if (EPI == 1) {
#pragma unroll
        for (int t = 0; t < 4; t++) {
            int u = tid + 256 * t;
            arr4[t] = u >> 3;
            aq4[t] = u & 7;
            int r = g_gathered[m0 + arr4[t]];
            arow[t] = (r >= 0) ? (Axf + (size_t)r * K) : (const float*)0;
        }
    } else {
#pragma unroll
        for (int t = 0; t < 2; t++) {
            int u = tid + 256 * t;
            a2r[t] = u >> 2;           // 0..127
            a2c[t] = u & 3;            // 0..3 (uint4 chunk within the 32-half row chunk)
            gA2[t] = g_buf + OFF_H + (size_t)(m0 + a2r[t]) * (K / 2) + a2c[t] * 4;
        }
    }
    // ---- B load slots: 32 krows x 16 uint4/row = 512; u = tid+256*t (t<2):
    //   krow = u>>4, chunk = u&15
    int bkr[2], bcq[2];
    const float* gB[2];
#pragma unroll
    for (int t = 0; t < 2; t++) {
        int u = tid + 256 * t;
        bkr[t] = u >> 4;
        bcq[t] = u & 15;
        gB[t] = Bp + (size_t)bkr[t] * (NB / 2) + n0 / 2 + bcq[t] * 4;
    }

    wmma::fragment<wmma::accumulator, 16, 16, 16, float> cf[2][4];
#pragma unroll
    for (int i = 0; i < 2; i++)
#pragma unroll
        for (int j = 0; j < 4; j++) wmma::fill_fragment(cf[i][j], 0.f);

    float4 pa[4];
    uint4  pa2[2];
    uint4  pb[2];

    // prefetch + store chunk 0 -> buffer 0
    if (EPI == 1) {
#pragma unroll
        for (int t = 0; t < 4; t++)
            pa[t] = arow[t] ? *reinterpret_cast<const float4*>(arow[t] + aq4[t] * 4)
                            : make_float4(0.f, 0.f, 0.f, 0.f);
    } else {
#pragma unroll
        for (int t = 0; t < 2; t++) pa2[t] = *reinterpret_cast<const uint4*>(gA2[t]);
    }
#pragma unroll
    for (int t = 0; t < 2; t++) pb[t] = *reinterpret_cast<const uint4*>(gB[t]);

    if (EPI == 1) {
#pragma unroll
        for (int t = 0; t < 4; t++) {
            __half2 h01 = __floats2half2_rn(pa[t].x, pa[t].y);
            __half2 h23 = __floats2half2_rn(pa[t].z, pa[t].w);
            *reinterpret_cast<__half2*>(&As[0][arr4[t]][aq4[t] * 4])     = h01;
            *reinterpret_cast<__half2*>(&As[0][arr4[t]][aq4[t] * 4 + 2]) = h23;
        }
    } else {
#pragma unroll
        for (int t = 0; t < 2; t++)
            *reinterpret_cast<uint4*>(&As[0][a2r[t]][a2c[t] * 8]) = pa2[t];
    }
#pragma unroll
    for (int t = 0; t < 2; t++)
        *reinterpret_cast<uint4*>(&Bs[0][bkr[t]][bcq[t] * 8]) = pb[t];

    const int NCH = K / BK;
    for (int ch = 0; ch < NCH; ch++) {
        __syncthreads();
        const int buf = ch & 1;

        // prefetch chunk ch+1
        if (ch + 1 < NCH) {
            int kn = (ch + 1) * BK;
            if (EPI == 1) {
#pragma unroll
                for (int t = 0; t < 4; t++)
                    pa[t] = arow[t] ? *reinterpret_cast<const float4*>(arow[t] + kn + aq4[t] * 4)
                                    : make_float4(0.f, 0.f, 0.f, 0.f);
            } else {
#pragma unroll
                for (int t = 0; t < 2; t++)
                    pa2[t] = *reinterpret_cast<const uint4*>(gA2[t] + kn / 2);
            }
#pragma unroll
            for (int t = 0; t < 2; t++)
                pb[t] = *reinterpret_cast<const uint4*>(gB[t] + (size_t)kn * (NB / 2));
        }

        // compute: two 16-k steps
#pragma unroll
        for (int ks = 0; ks < 2; ks++) {
            wmma::fragment<wmma::matrix_a, 16, 16, 16, __half, wmma::row_major> af[2];
            wmma::fragment<wmma::matrix_b, 16, 16, 16, __half, wmma::row_major> bf[4];
#pragma unroll
            for (int mf = 0; mf < 2; mf++)
                wmma::load_matrix_sync(af[mf], &As[buf][wm * 32 + mf * 16][ks * 16], 40);
#pragma unroll
            for (int nf = 0; nf < 4; nf++)
                wmma::load_matrix_sync(bf[nf], &Bs[buf][ks * 16][wn * 64 + nf * 16], 136);
#pragma unroll
            for (int mf = 0; mf < 2; mf++)
#pragma unroll
                for (int nf = 0; nf < 4; nf++)
                    wmma::mma_sync(cf[mf][nf], af[mf], bf[nf], cf[mf][nf]);
        }

        // store chunk ch+1 into the other buffer
        if (ch + 1 < NCH) {
            const int nb = (ch + 1) & 1;
            if (EPI == 1) {
#pragma unroll
                for (int t = 0; t < 4; t++) {
                    __half2 h01 = __floats2half2_rn(pa[t].x, pa[t].y);
                    __half2 h23 = __floats2half2_rn(pa[t].z, pa[t].w);
                    *reinterpret_cast<__half2*>(&As[nb][arr4[t]][aq4[t] * 4])     = h01;
                    *reinterpret_cast<__half2*>(&As[nb][arr4[t]][aq4[t] * 4 + 2]) = h23;
                }
            } else {
#pragma unroll
                for (int t = 0; t < 2; t++)
                    *reinterpret_cast<uint4*>(&As[nb][a2r[t]][a2c[t] * 8]) = pa2[t];
            }
#pragma unroll
            for (int t = 0; t < 2; t++)
                *reinterpret_cast<uint4*>(&Bs[nb][bkr[t]][bcq[t] * 8]) = pb[t];
        }
    }

    // ---------------- epilogue: per-warp 16x16 staging (ld=20) ----------------
#pragma unroll
    for (int mf = 0; mf < 2; mf++)
#pragma unroll
        for (int nf = 0; nf < 4; nf++) {
            wmma::store_matrix_sync(&stage[wid][0][0], cf[mf][nf], 20, wmma::mem_row_major);
            __syncwarp();
            int rb = m0 + wm * 32 + mf * 16;
            int cb = n0 + wn * 64 + nf * 16;
#pragma unroll
            for (int i = 0; i < 4; i++) {
                int p = lane + i * 32;
                int rr = p >> 3, cc = (p & 7) * 2;
                int row = rb + rr;
                int col = cb + cc;
                float v0 = stage[wid][rr][cc]     + bp[col];
                float v1 = stage[wid][rr][cc + 1] + bp[col + 1];
                if (EPI == 1) {
                    v0 = fmaxf(v0, 0.f);
                    v1 = fmaxf(v1, 0.f);
                    g_buf[OFF_H + (size_t)row * (HID / 2) + col / 2] = pack2(v0, v1);
                } else {
                    int r = g_gathered[row];
                    if (r >= 0)
                        *reinterpret_cast<float2*>(Cout + (size_t)r * NB + col) =
                            make_float2(v0, v1);
                }
            }
            __syncwarp();
        }
}

__global__ void k_stats(float* out, int out_size)
{
    int i = threadIdx.x;
    if (i < NE && out_size >= BTOK * OUTD + NE)
        out[(size_t)BTOK * OUTD + i] = (float)g_counts[i];
}

// ---------------- launch (8 launches, 8 kernel functions) ----------------
extern "C" void kernel_launch(void* const* d_in, const int* in_sizes, int n_in,
                              void* d_out, int out_size)
{
    const float* x   = (const float*)d_in[0];
    const float* rw1 = (const float*)d_in[1];
    const float* rb1 = (const float*)d_in[2];
    const float* rw2 = (const float*)d_in[3];
    const float* rb2 = (const float*)d_in[4];
    const float* ew1 = (const float*)d_in[5];
    const float* eb1 = (const float*)d_in[6];
    const float* ew2 = (const float*)d_in[7];
    const float* eb2 = (const float*)d_in[8];
    float* out = (float*)d_out;

    (void)in_sizes; (void)n_in;

    k_init<<<(W1Q + 255) / 256, 256>>>(ew1, ew2);

    k_router<<<dim3(1, BTOK / 128, KPARTS), 256>>>(x, rw1);
    k_logits<<<BTOK / 128, 128>>>(rb1, rw2, rb2);
    k_offsets<<<1, 1>>>();
    k_scatter<<<BTOK / 256, 256>>>();

    // GEMM1: h(packed) = fp16(relu(Xg @ W1[e] + b1[e]))
    wgemm<IND, HID, 1><<<dim3(HID / 128, MTILES), 256>>>(x, eb1, nullptr);

    // GEMM2: out[token] = h @ W2[e] + b2[e]
    wgemm<HID, OUTD, 2><<<dim3(OUTD / 128, MTILES), 256>>>(nullptr, eb2, out);

    k_stats<<<1, 32>>>(out, out_size);
}

// round 17
// speedup vs baseline: 1.4077x; 1.0331x over previous
#include <cuda_runtime.h>
#include <cuda_fp16.h>
#include <mma.h>
#include <cstdint>

using namespace nvcuda;

#define BTOK 8192
#define IND  1024
#define HID  4096
#define OUTD 1024
#define RHD  128
#define NE   3
#define GCAP 8448
#define MTILES (GCAP / 128)  // 66
#define KPARTS 4

// single fused scratch (float-typed), offsets in floats:
#define OFF_H   ((size_t)0)                               // packed hidden (head = router partials)
#define OFF_XP  ((size_t)GCAP * HID / 2)                  // packed x tokens
#define OFF_W1P (OFF_XP + (size_t)BTOK * IND / 2)         // packed w1 [e][k][n]
#define OFF_W2P (OFF_W1P + (size_t)NE * IND * HID / 2)    // packed w2 [e][k][n]
#define BUFSZ   (OFF_W2P + (size_t)NE * HID * OUTD / 2)   // ~34.1M floats = 136.3 MB
#define W1Q     (NE * IND * HID / 4)                      // 3,145,728
#define W2Q     (NE * HID * OUTD / 4)
#define XQ      (BTOK * IND / 4)                          // 2,097,152

// ---------------- device scratch: 7 globals (clean signature) ----------------
__device__ int   g_selected[BTOK];
__device__ int   g_counts[NE];
__device__ int   g_cursor[NE];
__device__ int   g_off[NE + 1];
__device__ int   g_total;
__device__ int   g_gathered[GCAP];
__device__ float g_buf[BUFSZ];

__device__ __forceinline__ float pack2(float a, float b) {
    __half2 h = __floats2half2_rn(a, b);
    uint32_t u = *reinterpret_cast<uint32_t*>(&h);
    return __uint_as_float(u);
}

// ---------------- init + pack x, w1, w2 to fp16 ----------------
__global__ void k_init(const float* __restrict__ x, const float* __restrict__ ew1,
                       const float* __restrict__ ew2)
{
    int i = blockIdx.x * blockDim.x + threadIdx.x;
    if (i < GCAP) g_gathered[i] = -1;
    if (i < NE) { g_counts[i] = 0; g_cursor[i] = 0; }
    if (i < XQ) {
        float4 v = *reinterpret_cast<const float4*>(x + (size_t)i * 4);
        *reinterpret_cast<float2*>(g_buf + OFF_XP + (size_t)i * 2) =
            make_float2(pack2(v.x, v.y), pack2(v.z, v.w));
    }
    if (i < W1Q) {
        float4 v = *reinterpret_cast<const float4*>(ew1 + (size_t)i * 4);
        *reinterpret_cast<float2*>(g_buf + OFF_W1P + (size_t)i * 2) =
            make_float2(pack2(v.x, v.y), pack2(v.z, v.w));
    }
    if (i < W2Q) {
        float4 v = *reinterpret_cast<const float4*>(ew2 + (size_t)i * 4);
        *reinterpret_cast<float2*>(g_buf + OFF_W2P + (size_t)i * 2) =
            make_float2(pack2(v.x, v.y), pack2(v.z, v.w));
    }
}

// ---------------- router fp32 GEMM, K-split x4 ----------------
__global__ __launch_bounds__(256)
void k_router(const float* __restrict__ x, const float* __restrict__ w1)
{
    const int BK = 16;
    __shared__ float As[BK][128];
    __shared__ float Bs[BK][128];
    const int m0 = blockIdx.y * 128;
    const int part = blockIdx.z;
    const int kbase = part * (IND / KPARTS);
    const int tid = threadIdx.x;
    const int tx = tid & 15, ty = tid >> 4;

    float c[8][8];
#pragma unroll
    for (int i = 0; i < 8; i++)
#pragma unroll
        for (int j = 0; j < 8; j++) c[i][j] = 0.f;

    for (int k0 = 0; k0 < IND / KPARTS; k0 += BK) {
#pragma unroll
        for (int t = 0; t < 2; t++) {
            int lin = tid + t * 256;
            int row = lin >> 2, kq = (lin & 3) * 4;
            float4 v = *reinterpret_cast<const float4*>(
                x + (size_t)(m0 + row) * IND + kbase + k0 + kq);
            As[kq + 0][row] = v.x; As[kq + 1][row] = v.y;
            As[kq + 2][row] = v.z; As[kq + 3][row] = v.w;
        }
#pragma unroll
        for (int t = 0; t < 2; t++) {
            int lin = tid + t * 256;
            int kk = lin >> 5, nq = (lin & 31) * 4;
            float4 v = *reinterpret_cast<const float4*>(
                w1 + (size_t)(kbase + k0 + kk) * RHD + nq);
            *reinterpret_cast<float4*>(&Bs[kk][nq]) = v;
        }
        __syncthreads();
#pragma unroll
        for (int kk = 0; kk < BK; kk++) {
            float a[8], b[8];
            float4 a0 = *reinterpret_cast<const float4*>(&As[kk][ty * 8]);
            float4 a1 = *reinterpret_cast<const float4*>(&As[kk][ty * 8 + 4]);
            float4 b0 = *reinterpret_cast<const float4*>(&Bs[kk][tx * 8]);
            float4 b1 = *reinterpret_cast<const float4*>(&Bs[kk][tx * 8 + 4]);
            a[0]=a0.x; a[1]=a0.y; a[2]=a0.z; a[3]=a0.w;
            a[4]=a1.x; a[5]=a1.y; a[6]=a1.z; a[7]=a1.w;
            b[0]=b0.x; b[1]=b0.y; b[2]=b0.z; b[3]=b0.w;
            b[4]=b1.x; b[5]=b1.y; b[6]=b1.z; b[7]=b1.w;
#pragma unroll
            for (int i = 0; i < 8; i++)
#pragma unroll
                for (int j = 0; j < 8; j++)
                    c[i][j] = fmaf(a[i], b[j], c[i][j]);
        }
        __syncthreads();
    }
    float* dst = g_buf + (size_t)part * BTOK * RHD;
#pragma unroll
    for (int i = 0; i < 8; i++) {
        float* p = dst + (size_t)(m0 + ty * 8 + i) * RHD + tx * 8;
        *reinterpret_cast<float4*>(p)     = make_float4(c[i][0], c[i][1], c[i][2], c[i][3]);
        *reinterpret_cast<float4*>(p + 4) = make_float4(c[i][4], c[i][5], c[i][6], c[i][7]);
    }
}

// ---------------- logits ----------------
__global__ void k_logits(const float* __restrict__ b1, const float* __restrict__ w2,
                         const float* __restrict__ b2)
{
    __shared__ float w2s[RHD * NE];
    __shared__ float b1s[RHD];
    __shared__ float b2s[NE];
    int tid = threadIdx.x;
    for (int i = tid; i < RHD * NE; i += 128) w2s[i] = w2[i];
    if (tid < RHD) b1s[tid] = b1[tid];
    if (tid < NE) b2s[tid] = b2[tid];
    __syncthreads();

    int token = blockIdx.x * 128 + tid;
    if (token >= BTOK) return;
    const float* p0 = g_buf + (size_t)token * RHD;
    const size_t PS = (size_t)BTOK * RHD;
    float a0 = b2s[0], a1 = b2s[1], a2 = b2s[2];
#pragma unroll 8
    for (int k = 0; k < RHD; k++) {
        float v = p0[k] + p0[PS + k] + p0[2 * PS + k] + p0[3 * PS + k] + b1s[k];
        v = fmaxf(v, 0.f);
        a0 = fmaf(v, w2s[k * NE + 0], a0);
        a1 = fmaf(v, w2s[k * NE + 1], a1);
        a2 = fmaf(v, w2s[k * NE + 2], a2);
    }
    int sel = 0; float best = a0;
    if (a1 > best) { best = a1; sel = 1; }
    if (a2 > best) { best = a2; sel = 2; }
    g_selected[token] = sel;
    atomicAdd(&g_counts[sel], 1);
}

__global__ void k_offsets()
{
    int off = 0;
    g_off[0] = 0;
    for (int e = 0; e < NE; e++) {
        int mpad = ((g_counts[e] + 127) / 128) * 128;
        off += mpad;
        g_off[e + 1] = off;
    }
    g_total = off;
}

__global__ void k_scatter()
{
    int b = blockIdx.x * 256 + threadIdx.x;
    if (b >= BTOK) return;
    int e = g_selected[b];
    int pos = atomicAdd(&g_cursor[e], 1);
    g_gathered[g_off[e] + pos] = b;
}

// ---------------- WMMA GEMM, 128x128 tile, BK=32, double-buffered, packed A+B ----
// EPI==1: A = packed x via g_gathered (zero-fill pads), B = packed w1;
//         epilogue -> packed fp16(relu(D+b1)) into g_buf[OFF_H].
// EPI==2: A = packed h, B = packed w2; epilogue -> out[g_gathered[row]] = D + b2.
template<int K, int NB, int EPI>
__global__ __launch_bounds__(256)
void wgemm(const float* __restrict__ biasb, float* __restrict__ Cout)
{
    const int BK = 32;
    __shared__ __align__(16) __half As[2][128][40];   // row-major, ldm 40
    __shared__ __align__(16) __half Bs[2][BK][136];   // row-major, ldm 136
    __shared__ __align__(16) float stage[8][16][20];  // total smem 48128 B

    const int m0 = blockIdx.y * 128;
    if (m0 >= g_total) return;
    int e = (m0 >= g_off[1]) ? ((m0 >= g_off[2]) ? 2 : 1) : 0;
    const int n0 = blockIdx.x * 128;
    const float* Bp = (EPI == 1 ? g_buf + OFF_W1P : g_buf + OFF_W2P) + (size_t)e * K * NB / 2;
    const float* bp = biasb + (size_t)e * NB;

    const int tid = threadIdx.x;
    const int wid = tid >> 5, lane = tid & 31;
    const int wm = wid & 3, wn = wid >> 2;   // 4x2 warp grid, 32x64 warp tile

    // ---- A load slots (packed): 128 rows x 4 uint4/row = 512 slots;
    //      u = tid+256*t (t<2): row = u>>2, chunk = u&3; half-cols chunk*8..+7
    int a_r[2], a_c[2];
    const float* gA[2];
#pragma unroll
    for (int t = 0; t < 2; t++) {
        int u = tid + 256 * t;
        a_r[t] = u >> 2;
        a_c[t] = u & 3;
        if (EPI == 1) {
            int r = g_gathered[m0 + a_r[t]];
            gA[t] = (r >= 0) ? (g_buf + OFF_XP + (size_t)r * (K / 2) + a_c[t] * 4)
                             : (const float*)0;
        } else {
            gA[t] = g_buf + OFF_H + (size_t)(m0 + a_r[t]) * (K / 2) + a_c[t] * 4;
        }
    }
    // ---- B load slots: 32 krows x 16 uint4/row = 512; u = tid+256*t (t<2):
    int bkr[2], bcq[2];
    const float* gB[2];
#pragma unroll
    for (int t = 0; t < 2; t++) {
        int u = tid + 256 * t;
        bkr[t] = u >> 4;
        bcq[t] = u & 15;
        gB[t] = Bp + (size_t)bkr[t] * (NB / 2) + n0 / 2 + bcq[t] * 4;
    }

    wmma::fragment<wmma::accumulator, 16, 16, 16, float> cf[2][4];
#pragma unroll
    for (int i = 0; i < 2; i++)
#pragma unroll
        for (int j = 0; j < 4; j++) wmma::fill_fragment(cf[i][j], 0.f);

    uint4 pa[2], pb[2];
    const uint4 z4 = make_uint4(0u, 0u, 0u, 0u);

    // prefetch + store chunk 0 -> buffer 0
#pragma unroll
    for (int t = 0; t < 2; t++) {
        pa[t] = gA[t] ? *reinterpret_cast<const uint4*>(gA[t]) : z4;
        pb[t] = *reinterpret_cast<const uint4*>(gB[t]);
    }
#pragma unroll
    for (int t = 0; t < 2; t++) {
        *reinterpret_cast<uint4*>(&As[0][a_r[t]][a_c[t] * 8]) = pa[t];
        *reinterpret_cast<uint4*>(&Bs[0][bkr[t]][bcq[t] * 8]) = pb[t];
    }

    const int NCH = K / BK;
    for (int ch = 0; ch < NCH; ch++) {
        __syncthreads();
        const int buf = ch & 1;

        // prefetch chunk ch+1
        if (ch + 1 < NCH) {
            int kn = (ch + 1) * BK;
#pragma unroll
            for (int t = 0; t < 2; t++) {
                pa[t] = gA[t] ? *reinterpret_cast<const uint4*>(gA[t] + kn / 2) : z4;
                pb[t] = *reinterpret_cast<const uint4*>(gB[t] + (size_t)kn * (NB / 2));
            }
        }

        // compute: two 16-k steps
#pragma unroll
        for (int ks = 0; ks < 2; ks++) {
            wmma::fragment<wmma::matrix_a, 16, 16, 16, __half, wmma::row_major> af[2];
            wmma::fragment<wmma::matrix_b, 16, 16, 16, __half, wmma::row_major> bf[4];
#pragma unroll
            for (int mf = 0; mf < 2; mf++)
                wmma::load_matrix_sync(af[mf], &As[buf][wm * 32 + mf * 16][ks * 16], 40);
#pragma unroll
            for (int nf = 0; nf < 4; nf++)
                wmma::load_matrix_sync(bf[nf], &Bs[buf][ks * 16][wn * 64 + nf * 16], 136);
#pragma unroll
            for (int mf = 0; mf < 2; mf++)
#pragma unroll
                for (int nf = 0; nf < 4; nf++)
                    wmma::mma_sync(cf[mf][nf], af[mf], bf[nf], cf[mf][nf]);
        }

        // store chunk ch+1 into the other buffer
        if (ch + 1 < NCH) {
            const int nb = (ch + 1) & 1;
#pragma unroll
            for (int t = 0; t < 2; t++) {
                *reinterpret_cast<uint4*>(&As[nb][a_r[t]][a_c[t] * 8]) = pa[t];
                *reinterpret_cast<uint4*>(&Bs[nb][bkr[t]][bcq[t] * 8]) = pb[t];
            }
        }
    }

    // ---------------- epilogue: per-warp 16x16 staging (ld=20) ----------------
#pragma unroll
    for (int mf = 0; mf < 2; mf++)
#pragma unroll
        for (int nf = 0; nf < 4; nf++) {
            wmma::store_matrix_sync(&stage[wid][0][0], cf[mf][nf], 20, wmma::mem_row_major);
            __syncwarp();
            int rb = m0 + wm * 32 + mf * 16;
            int cb = n0 + wn * 64 + nf * 16;
#pragma unroll
            for (int i = 0; i < 4; i++) {
                int p = lane + i * 32;
                int rr = p >> 3, cc = (p & 7) * 2;
                int row = rb + rr;
                int col = cb + cc;
                float v0 = stage[wid][rr][cc]     + bp[col];
                float v1 = stage[wid][rr][cc + 1] + bp[col + 1];
                if (EPI == 1) {
                    v0 = fmaxf(v0, 0.f);
                    v1 = fmaxf(v1, 0.f);
                    g_buf[OFF_H + (size_t)row * (HID / 2) + col / 2] = pack2(v0, v1);
                } else {
                    int r = g_gathered[row];
                    if (r >= 0)
                        *reinterpret_cast<float2*>(Cout + (size_t)r * NB + col) =
                            make_float2(v0, v1);
                }
            }
            __syncwarp();
        }
}

__global__ void k_stats(float* out, int out_size)
{
    int i = threadIdx.x;
    if (i < NE && out_size >= BTOK * OUTD + NE)
        out[(size_t)BTOK * OUTD + i] = (float)g_counts[i];
}

// ---------------- launch (8 launches, 8 kernel functions) ----------------
extern "C" void kernel_launch(void* const* d_in, const int* in_sizes, int n_in,
                              void* d_out, int out_size)
{
    const float* x   = (const float*)d_in[0];
    const float* rw1 = (const float*)d_in[1];
    const float* rb1 = (const float*)d_in[2];
    const float* rw2 = (const float*)d_in[3];
    const float* rb2 = (const float*)d_in[4];
    const float* ew1 = (const float*)d_in[5];
    const float* eb1 = (const float*)d_in[6];
    const float* ew2 = (const float*)d_in[7];
    const float* eb2 = (const float*)d_in[8];
    float* out = (float*)d_out;

    (void)in_sizes; (void)n_in;

    k_init<<<(W1Q + 255) / 256, 256>>>(x, ew1, ew2);

    k_router<<<dim3(1, BTOK / 128, KPARTS), 256>>>(x, rw1);
    k_logits<<<BTOK / 128, 128>>>(rb1, rw2, rb2);
    k_offsets<<<1, 1>>>();
    k_scatter<<<BTOK / 256, 256>>>();

    // GEMM1: h(packed) = fp16(relu(Xg @ W1[e] + b1[e]))
    wgemm<IND, HID, 1><<<dim3(HID / 128, MTILES), 256>>>(eb1, nullptr);

    // GEMM2: out[token] = h @ W2[e] + b2[e]
    wgemm<HID, OUTD, 2><<<dim3(OUTD / 128, MTILES), 256>>>(eb2, out);

    k_stats<<<1, 32>>>(out, out_size);
}